// round 2
// baseline (speedup 1.0000x reference)
#include <cuda_runtime.h>
#include <cuda_bf16.h>
#include <math.h>

#define NN      8192
#define NFEAT   512
#define NHID    64
#define NHEADS  8
#define NCLASS  40
#define CHUNK   128
#define NCHUNKS (NN / CHUNK)   // 64

// ----------------------------- scratch (static device globals) ---------------
__device__ float g_Bpack[NFEAT * NHEADS * NHID];
__device__ float g_Wh1[NN * NHEADS * NHID];
__device__ float g_H[NN * NHEADS * NHID];
__device__ float g_Wh2[NN * NCLASS];
__device__ float g_O2[NN * NCLASS];
__device__ float g_f1[NHEADS * NN];
__device__ float g_f2[NHEADS * NN];
__device__ float g_key[NHEADS * NN];
__device__ int   g_perm[NHEADS * NN];
__device__ float g_w[NHEADS * NN];
__device__ float g_mean[NHEADS * 64];
__device__ float g_P[NHEADS * (NN + 1) * NHID];
__device__ float g_S[NHEADS * (NN + 1)];
__device__ float g_P2[(NN + 1) * NCLASS];
__device__ float g_S2[(NN + 1)];
__device__ float g_chunkP[NHEADS * NCHUNKS * 64];
__device__ float g_chunkS[NHEADS * NCHUNKS];

// ----------------------------- kernels --------------------------------------

__global__ void repack_W_kernel(const float* __restrict__ Wh, float* __restrict__ Bp) {
    int idx = blockIdx.x * blockDim.x + threadIdx.x;
    if (idx < NFEAT * NHEADS * NHID) {
        int n = idx % (NHEADS * NHID);
        int k = idx / (NHEADS * NHID);
        int h = n / NHID, d = n % NHID;
        Bp[idx] = Wh[(h * NFEAT + k) * NHID + d];
    }
}

#define BM 128
#define BN 128
#define BKK 8
#define TM 8
#define TN 8
__global__ __launch_bounds__(256) void sgemm_kernel(
    int M, int Ncols, int K,
    const float* __restrict__ A, const float* __restrict__ B, float* __restrict__ C)
{
    __shared__ float As[BKK][BM];
    __shared__ float Bs[BKK][BN];
    int tid = threadIdx.x;
    int tx = tid % (BN / TN);
    int ty = tid / (BN / TN);
    int bm = blockIdx.y * BM, bn = blockIdx.x * BN;
    float acc[TM][TN];
#pragma unroll
    for (int i = 0; i < TM; i++)
#pragma unroll
        for (int j = 0; j < TN; j++) acc[i][j] = 0.f;

    for (int k0 = 0; k0 < K; k0 += BKK) {
        {
            int aRow = tid >> 1, aCol = (tid & 1) * 4;
#pragma unroll
            for (int i = 0; i < 4; i++) {
                float v = 0.f;
                int gr = bm + aRow, gc = k0 + aCol + i;
                if (gr < M) v = A[(size_t)gr * K + gc];
                As[aCol + i][aRow] = v;
            }
            int bRow = tid >> 5, bCol = (tid & 31) * 4;
#pragma unroll
            for (int i = 0; i < 4; i++) {
                float v = 0.f;
                int gc = bn + bCol + i;
                if (gc < Ncols) v = B[(size_t)(k0 + bRow) * Ncols + gc];
                Bs[bRow][bCol + i] = v;
            }
        }
        __syncthreads();
#pragma unroll
        for (int kk = 0; kk < BKK; kk++) {
            float ar[TM], br[TN];
#pragma unroll
            for (int i = 0; i < TM; i++) ar[i] = As[kk][ty * TM + i];
#pragma unroll
            for (int j = 0; j < TN; j++) br[j] = Bs[kk][tx * TN + j];
#pragma unroll
            for (int i = 0; i < TM; i++)
#pragma unroll
                for (int j = 0; j < TN; j++) acc[i][j] += ar[i] * br[j];
        }
        __syncthreads();
    }
#pragma unroll
    for (int i = 0; i < TM; i++) {
        int gr = bm + ty * TM + i;
        if (gr >= M) continue;
#pragma unroll
        for (int j = 0; j < TN; j++) {
            int gc = bn + tx * TN + j;
            if (gc < Ncols) C[(size_t)gr * Ncols + gc] = acc[i][j];
        }
    }
}

__global__ void compute_f_kernel(
    const float* __restrict__ Wh, int ld, int F,
    const float* __restrict__ a, int aStride, int nHeads,
    float* __restrict__ f1, float* __restrict__ f2)
{
    int warpId = (blockIdx.x * blockDim.x + threadIdx.x) >> 5;
    int lane = threadIdx.x & 31;
    int total = NN * nHeads;
    if (warpId >= total) return;
    int h = warpId % nHeads;
    int i = warpId / nHeads;
    const float* av = a + h * aStride;
    const float* row = Wh + (size_t)i * ld + h * F;
    float s1 = 0.f, s2 = 0.f;
    for (int d = lane; d < F; d += 32) {
        float v = row[d];
        s1 += v * av[d];
        s2 += v * av[F + d];
    }
#pragma unroll
    for (int o = 16; o; o >>= 1) {
        s1 += __shfl_down_sync(0xFFFFFFFFu, s1, o);
        s2 += __shfl_down_sync(0xFFFFFFFFu, s2, o);
    }
    if (lane == 0) { f1[h * NN + i] = s1; f2[h * NN + i] = s2; }
}

// -------- fast register/shuffle bitonic sort (descending), 8192 keys/block ---
// Packs (ordered_key << 32) | original_index into uint64; sorts descending.
// Also emits w[r] = exp(key[r] - key[0]) (key[0] = max after descending sort).
__device__ __forceinline__ unsigned int ord_of_float(float f) {
    unsigned int u = __float_as_uint(f);
    return u ^ ((u & 0x80000000u) ? 0xFFFFFFFFu : 0x80000000u);
}
__device__ __forceinline__ float float_of_ord(unsigned int o) {
    o = (o & 0x80000000u) ? (o ^ 0x80000000u) : ~o;
    return __uint_as_float(o);
}

__global__ __launch_bounds__(1024) void fast_sort_kernel(
    const float* __restrict__ f2src, float* __restrict__ keyOut,
    int* __restrict__ permOut, float* __restrict__ wOut)
{
    extern __shared__ unsigned long long sbuf[];   // 8192 * 8B = 64 KB
    int h = blockIdx.x;
    int t = threadIdx.x;
    const float* src = f2src + h * NN;
    unsigned long long v[8];
#pragma unroll
    for (int r = 0; r < 8; r++) {
        int g = t * 8 + r;
        v[r] = ((unsigned long long)ord_of_float(src[g]) << 32) | (unsigned int)g;
    }

    for (int k = 2; k <= NN; k <<= 1) {
        for (int j = k >> 1; j > 0; j >>= 1) {
            if (j >= 8) {
                int p = j >> 3;                              // partner thread distance
                bool dir = (((t * 8) & k) == 0);             // k >= 16 here: uniform over r
                bool lower = ((t & p) == 0);
                bool keepMax = (lower == dir);
                if (p < 32) {
#pragma unroll
                    for (int r = 0; r < 8; r++) {
                        unsigned int lo = (unsigned int)v[r];
                        unsigned int hi = (unsigned int)(v[r] >> 32);
                        unsigned int olo = __shfl_xor_sync(0xFFFFFFFFu, lo, p);
                        unsigned int ohi = __shfl_xor_sync(0xFFFFFFFFu, hi, p);
                        unsigned long long o = ((unsigned long long)ohi << 32) | olo;
                        bool mineMax = v[r] > o;
                        v[r] = (mineMax == keepMax) ? v[r] : o;
                    }
                } else {
                    __syncthreads();   // protect prior reads before overwrite
#pragma unroll
                    for (int r = 0; r < 8; r++) sbuf[r * 1024 + t] = v[r];
                    __syncthreads();
                    int pt = t ^ p;
#pragma unroll
                    for (int r = 0; r < 8; r++) {
                        unsigned long long o = sbuf[r * 1024 + pt];
                        bool mineMax = v[r] > o;
                        v[r] = (mineMax == keepMax) ? v[r] : o;
                    }
                }
            } else {
#pragma unroll
                for (int r = 0; r < 8; r++) {
                    if ((r & j) == 0) {
                        int rr = r | j;
                        bool dir = (((t * 8 + r) & k) == 0);
                        unsigned long long a = v[r], b = v[rr];
                        bool sw = dir ? (a < b) : (a > b);
                        if (sw) { v[r] = b; v[rr] = a; }
                    }
                }
            }
        }
    }

    // broadcast the max key (global index 0)
    __syncthreads();
    if (t == 0) sbuf[0] = v[0];
    __syncthreads();
    float kmax = float_of_ord((unsigned int)(sbuf[0] >> 32));

#pragma unroll
    for (int r = 0; r < 8; r++) {
        int g = t * 8 + r;
        float kf = float_of_ord((unsigned int)(v[r] >> 32));
        keyOut[h * NN + g] = kf;
        permOut[h * NN + g] = (int)(unsigned int)(v[r] & 0xFFFFFFFFu);
        wOut[h * NN + g] = expf(kf - kmax);
    }
}

__global__ void col_mean_kernel(const float* __restrict__ Wh, int ld, int F, float* __restrict__ mean) {
    int d = blockIdx.x, h = blockIdx.y;
    float s = 0.f;
    for (int i = threadIdx.x; i < NN; i += blockDim.x)
        s += Wh[(size_t)i * ld + h * F + d];
    __shared__ float red[256];
    red[threadIdx.x] = s;
    __syncthreads();
    for (int o = 128; o; o >>= 1) {
        if (threadIdx.x < o) red[threadIdx.x] += red[threadIdx.x + o];
        __syncthreads();
    }
    if (threadIdx.x == 0) mean[h * 64 + d] = red[0] / (float)NN;
}

__global__ void chunk_sums_kernel(
    const float* __restrict__ Wh, int ld, int F,
    const int* __restrict__ perm, const float* __restrict__ w,
    float* __restrict__ chunkP, float* __restrict__ chunkS)
{
    int c = blockIdx.x, h = blockIdx.y, d = threadIdx.x;
    const int* pm = perm + h * NN + c * CHUNK;
    const float* ww = w + h * NN + c * CHUNK;
    float acc = 0.f, accS = 0.f;
    for (int r = 0; r < CHUNK; r++) {
        float wr = ww[r];
        if (d < F) acc += wr * Wh[(size_t)pm[r] * ld + h * F + d];
        if (d == 0) accS += wr;
    }
    if (d < F) chunkP[(h * NCHUNKS + c) * 64 + d] = acc;
    if (d == 0) chunkS[h * NCHUNKS + c] = accS;
}

__global__ void scan_chunks_kernel(float* __restrict__ chunkP, float* __restrict__ chunkS, int F) {
    int h = blockIdx.x, d = threadIdx.x;
    if (d < F) {
        float acc = 0.f;
        for (int c = 0; c < NCHUNKS; c++) {
            int idx = (h * NCHUNKS + c) * 64 + d;
            float t = chunkP[idx]; chunkP[idx] = acc; acc += t;
        }
    }
    if (d == 0) {
        float acc = 0.f;
        for (int c = 0; c < NCHUNKS; c++) {
            int idx = h * NCHUNKS + c;
            float t = chunkS[idx]; chunkS[idx] = acc; acc += t;
        }
    }
}

__global__ void write_prefix_kernel(
    const float* __restrict__ Wh, int ld, int F,
    const int* __restrict__ perm, const float* __restrict__ w,
    const float* __restrict__ chunkP, const float* __restrict__ chunkS,
    float* __restrict__ P, float* __restrict__ S)
{
    int c = blockIdx.x, h = blockIdx.y, d = threadIdx.x;
    const int* pm = perm + h * NN + c * CHUNK;
    const float* ww = w + h * NN + c * CHUNK;
    float acc = (d < F) ? chunkP[(h * NCHUNKS + c) * 64 + d] : 0.f;
    float accS = chunkS[h * NCHUNKS + c];
    float* Ph = P + (size_t)h * (NN + 1) * F;
    float* Sh = S + (size_t)h * (NN + 1);
    for (int r = 0; r < CHUNK; r++) {
        float wr = ww[r];
        if (d < F) {
            acc += wr * Wh[(size_t)pm[r] * ld + h * F + d];
            Ph[(size_t)(c * CHUNK + r + 1) * F + d] = acc;
        }
        if (d == 0) { accS += wr; Sh[c * CHUNK + r + 1] = accS; }
    }
}

__global__ void apply_attn_kernel(
    const float* __restrict__ key, const float* __restrict__ f1,
    const float* __restrict__ P, const float* __restrict__ S,
    const float* __restrict__ mean, int F, int nHeads,
    float* __restrict__ out, int ldOut)
{
    int g = (blockIdx.x * blockDim.x + threadIdx.x) >> 6;
    int d = threadIdx.x & 63;
    int total = NN * nHeads;
    if (g >= total) return;
    int h = g % nHeads;
    int i = g / nHeads;
    const float* kh = key + h * NN;
    float t = f1[h * NN + i];
    int lo = 0, hi = NN;
    while (lo < hi) {
        int mid = (lo + hi) >> 1;
        if (t + kh[mid] > 0.f) lo = mid + 1; else hi = mid;
    }
    int c = lo;
    if (d < F) {
        float v;
        if (c > 0) {
            v = P[((size_t)h * (NN + 1) + c) * F + d] / S[(size_t)h * (NN + 1) + c];
        } else {
            v = mean[h * 64 + d];
        }
        v = (v > 0.f) ? v : (expf(v) - 1.f);
        out[(size_t)i * ldOut + h * F + d] = v;
    }
}

__global__ void log_softmax_kernel(const float* __restrict__ X, float* __restrict__ out) {
    int i = blockIdx.x * (blockDim.x >> 5) + (threadIdx.x >> 5);
    int lane = threadIdx.x & 31;
    if (i >= NN) return;
    const float* row = X + (size_t)i * NCLASS;
    float v0 = (lane < NCLASS) ? row[lane] : -INFINITY;
    float v1 = (lane + 32 < NCLASS) ? row[lane + 32] : -INFINITY;
    float mx = fmaxf(v0, v1);
#pragma unroll
    for (int o = 16; o; o >>= 1) mx = fmaxf(mx, __shfl_xor_sync(0xFFFFFFFFu, mx, o));
    float se = 0.f;
    if (lane < NCLASS) se += expf(v0 - mx);
    if (lane + 32 < NCLASS) se += expf(v1 - mx);
#pragma unroll
    for (int o = 16; o; o >>= 1) se += __shfl_xor_sync(0xFFFFFFFFu, se, o);
    float lse = mx + logf(se);
    if (lane < NCLASS) out[(size_t)i * NCLASS + lane] = v0 - lse;
    if (lane + 32 < NCLASS) out[(size_t)i * NCLASS + lane + 32] = v1 - lse;
}

// ----------------------------- host launcher --------------------------------
extern "C" void kernel_launch(void* const* d_in, const int* in_sizes, int n_in,
                              void* d_out, int out_size)
{
    const float* x       = (const float*)d_in[0];
    const float* W_heads = (const float*)d_in[2];
    const float* a_heads = (const float*)d_in[3];
    const float* W_out   = (const float*)d_in[4];
    const float* a_out   = (const float*)d_in[5];
    float* out = (float*)d_out;

    float *Bp, *Wh1, *H, *Wh2, *O2, *f1, *f2, *key, *w, *meanb, *P, *S, *P2, *S2, *chunkP, *chunkS;
    int* perm;
    cudaGetSymbolAddress((void**)&Bp,    g_Bpack);
    cudaGetSymbolAddress((void**)&Wh1,   g_Wh1);
    cudaGetSymbolAddress((void**)&H,     g_H);
    cudaGetSymbolAddress((void**)&Wh2,   g_Wh2);
    cudaGetSymbolAddress((void**)&O2,    g_O2);
    cudaGetSymbolAddress((void**)&f1,    g_f1);
    cudaGetSymbolAddress((void**)&f2,    g_f2);
    cudaGetSymbolAddress((void**)&key,   g_key);
    cudaGetSymbolAddress((void**)&perm,  g_perm);
    cudaGetSymbolAddress((void**)&w,     g_w);
    cudaGetSymbolAddress((void**)&meanb, g_mean);
    cudaGetSymbolAddress((void**)&P,     g_P);
    cudaGetSymbolAddress((void**)&S,     g_S);
    cudaGetSymbolAddress((void**)&P2,    g_P2);
    cudaGetSymbolAddress((void**)&S2,    g_S2);
    cudaGetSymbolAddress((void**)&chunkP, g_chunkP);
    cudaGetSymbolAddress((void**)&chunkS, g_chunkS);

    static bool attrDone = false;
    if (!attrDone) {
        cudaFuncSetAttribute(fast_sort_kernel,
                             cudaFuncAttributeMaxDynamicSharedMemorySize, 65536);
        attrDone = true;
    }

    // ---------------- layer 1 (8 heads fused) ----------------
    repack_W_kernel<<<(NFEAT * NHEADS * NHID + 255) / 256, 256>>>(W_heads, Bp);
    {
        dim3 grid((NHEADS * NHID + BN - 1) / BN, (NN + BM - 1) / BM);
        sgemm_kernel<<<grid, 256>>>(NN, NHEADS * NHID, NFEAT, x, Bp, Wh1);
    }
    compute_f_kernel<<<(NN * NHEADS * 32) / 128, 128>>>(Wh1, NHEADS * NHID, NHID,
                                                        a_heads, 2 * NHID, NHEADS, f1, f2);
    fast_sort_kernel<<<NHEADS, 1024, 65536>>>(f2, key, perm, w);
    col_mean_kernel<<<dim3(NHID, NHEADS), 256>>>(Wh1, NHEADS * NHID, NHID, meanb);
    chunk_sums_kernel<<<dim3(NCHUNKS, NHEADS), 64>>>(Wh1, NHEADS * NHID, NHID, perm, w, chunkP, chunkS);
    scan_chunks_kernel<<<NHEADS, 64>>>(chunkP, chunkS, NHID);
    write_prefix_kernel<<<dim3(NCHUNKS, NHEADS), 64>>>(Wh1, NHEADS * NHID, NHID, perm, w,
                                                       chunkP, chunkS, P, S);
    apply_attn_kernel<<<(NN * NHEADS * 64) / 256, 256>>>(key, f1, P, S, meanb, NHID, NHEADS,
                                                         H, NHEADS * NHID);

    // ---------------- layer 2 (output head, F = 40) ----------------
    {
        dim3 grid((NCLASS + BN - 1) / BN, (NN + BM - 1) / BM);
        sgemm_kernel<<<grid, 256>>>(NN, NCLASS, NHEADS * NHID, H, W_out, Wh2);
    }
    compute_f_kernel<<<(NN * 32 + 127) / 128, 128>>>(Wh2, NCLASS, NCLASS, a_out, 2 * NCLASS, 1, f1, f2);
    fast_sort_kernel<<<1, 1024, 65536>>>(f2, key, perm, w);
    col_mean_kernel<<<dim3(NCLASS, 1), 256>>>(Wh2, NCLASS, NCLASS, meanb);
    chunk_sums_kernel<<<dim3(NCHUNKS, 1), 64>>>(Wh2, NCLASS, NCLASS, perm, w, chunkP, chunkS);
    scan_chunks_kernel<<<1, 64>>>(chunkP, chunkS, NCLASS);
    write_prefix_kernel<<<dim3(NCHUNKS, 1), 64>>>(Wh2, NCLASS, NCLASS, perm, w, chunkP, chunkS, P2, S2);
    apply_attn_kernel<<<(NN * 64) / 256, 256>>>(key, f1, P2, S2, meanb, NCLASS, 1, O2, NCLASS);

    log_softmax_kernel<<<(NN + 7) / 8, 256>>>(O2, out);
}

// round 3
// speedup vs baseline: 1.3181x; 1.3181x over previous
#include <cuda_runtime.h>
#include <cuda_bf16.h>
#include <math.h>

#define NN      8192
#define NFEAT   512
#define NHID    64
#define NHEADS  8
#define NCLASS  40
#define CHUNK   128
#define NCHUNKS (NN / CHUNK)   // 64
#define SEG     2048

// ----------------------------- scratch (static device globals) ---------------
__device__ float g_Bpack[NFEAT * NHEADS * NHID];
__device__ float g_Wh1[NN * NHEADS * NHID];
__device__ float g_H[NN * NHEADS * NHID];
__device__ float g_Wh2[NN * NCLASS];
__device__ float g_O2[NN * NCLASS];
__device__ float g_f1[NHEADS * NN];
__device__ float g_key[NHEADS * NN];
__device__ int   g_perm[NHEADS * NN];
__device__ float g_w[NHEADS * NN];
__device__ float g_mean[NHEADS * 64];
__device__ float g_P[NHEADS * (NN + 1) * NHID];
__device__ float g_S[NHEADS * (NN + 1)];
__device__ float g_P2[(NN + 1) * NCLASS];
__device__ float g_S2[(NN + 1)];
__device__ float g_chunkP[NHEADS * NCHUNKS * 64];
__device__ float g_chunkS[NHEADS * NCHUNKS];
__device__ unsigned long long g_sortbuf[NHEADS * NN];

// ----------------------------- kernels --------------------------------------

__global__ void repack_W_kernel(const float* __restrict__ Wh, float* __restrict__ Bp) {
    int idx = blockIdx.x * blockDim.x + threadIdx.x;
    if (idx < NFEAT * NHEADS * NHID) {
        int n = idx % (NHEADS * NHID);
        int k = idx / (NHEADS * NHID);
        int h = n / NHID, d = n % NHID;
        Bp[idx] = Wh[(h * NFEAT + k) * NHID + d];
    }
}

#define BM 128
#define BN 128
#define BKK 8
#define TM 8
#define TN 8
__global__ __launch_bounds__(256) void sgemm_kernel(
    int M, int Ncols, int K,
    const float* __restrict__ A, const float* __restrict__ B, float* __restrict__ C)
{
    __shared__ float As[BKK][BM];
    __shared__ float Bs[BKK][BN];
    int tid = threadIdx.x;
    int tx = tid % (BN / TN);
    int ty = tid / (BN / TN);
    int bm = blockIdx.y * BM, bn = blockIdx.x * BN;
    float acc[TM][TN];
#pragma unroll
    for (int i = 0; i < TM; i++)
#pragma unroll
        for (int j = 0; j < TN; j++) acc[i][j] = 0.f;

    for (int k0 = 0; k0 < K; k0 += BKK) {
        {
            int aRow = tid >> 1, aCol = (tid & 1) * 4;
#pragma unroll
            for (int i = 0; i < 4; i++) {
                float v = 0.f;
                int gr = bm + aRow, gc = k0 + aCol + i;
                if (gr < M) v = A[(size_t)gr * K + gc];
                As[aCol + i][aRow] = v;
            }
            int bRow = tid >> 5, bCol = (tid & 31) * 4;
#pragma unroll
            for (int i = 0; i < 4; i++) {
                float v = 0.f;
                int gc = bn + bCol + i;
                if (gc < Ncols) v = B[(size_t)(k0 + bRow) * Ncols + gc];
                Bs[bRow][bCol + i] = v;
            }
        }
        __syncthreads();
#pragma unroll
        for (int kk = 0; kk < BKK; kk++) {
            float ar[TM], br[TN];
#pragma unroll
            for (int i = 0; i < TM; i++) ar[i] = As[kk][ty * TM + i];
#pragma unroll
            for (int j = 0; j < TN; j++) br[j] = Bs[kk][tx * TN + j];
#pragma unroll
            for (int i = 0; i < TM; i++)
#pragma unroll
                for (int j = 0; j < TN; j++) acc[i][j] += ar[i] * br[j];
        }
        __syncthreads();
    }
#pragma unroll
    for (int i = 0; i < TM; i++) {
        int gr = bm + ty * TM + i;
        if (gr >= M) continue;
#pragma unroll
        for (int j = 0; j < TN; j++) {
            int gc = bn + tx * TN + j;
            if (gc < Ncols) C[(size_t)gr * Ncols + gc] = acc[i][j];
        }
    }
}

// ---------- float <-> order-preserving uint ----------
__device__ __forceinline__ unsigned int ord_of_float(float f) {
    unsigned int u = __float_as_uint(f);
    return u ^ ((u & 0x80000000u) ? 0xFFFFFFFFu : 0x80000000u);
}
__device__ __forceinline__ float float_of_ord(unsigned int o) {
    o = (o & 0x80000000u) ? (o ^ 0x80000000u) : ~o;
    return __uint_as_float(o);
}

// f1 + packed sort key (ord(f2) << 32 | idx) per (row, head)
__global__ void compute_f_kernel(
    const float* __restrict__ Wh, int ld, int F,
    const float* __restrict__ a, int aStride, int nHeads,
    float* __restrict__ f1, unsigned long long* __restrict__ buf)
{
    int warpId = (blockIdx.x * blockDim.x + threadIdx.x) >> 5;
    int lane = threadIdx.x & 31;
    int total = NN * nHeads;
    if (warpId >= total) return;
    int h = warpId % nHeads;
    int i = warpId / nHeads;
    const float* av = a + h * aStride;
    const float* row = Wh + (size_t)i * ld + h * F;
    float s1 = 0.f, s2 = 0.f;
    for (int d = lane; d < F; d += 32) {
        float v = row[d];
        s1 += v * av[d];
        s2 += v * av[F + d];
    }
#pragma unroll
    for (int o = 16; o; o >>= 1) {
        s1 += __shfl_down_sync(0xFFFFFFFFu, s1, o);
        s2 += __shfl_down_sync(0xFFFFFFFFu, s2, o);
    }
    if (lane == 0) {
        f1[h * NN + i] = s1;
        buf[h * NN + i] = ((unsigned long long)ord_of_float(s2) << 32) | (unsigned int)i;
    }
}

// ---------- multi-block bitonic sort (descending), segment = 2048 ----------
// local sort: all stages k=2..SEG (every pair stays within a segment)
__global__ __launch_bounds__(512) void local_sort_kernel(unsigned long long* __restrict__ buf) {
    __shared__ unsigned long long s[SEG];
    int base = blockIdx.x * SEG;
    int ihead = base & (NN - 1);           // in-head index of segment start
    int t = threadIdx.x;
    for (int l = t; l < SEG; l += 512) s[l] = buf[base + l];
    __syncthreads();
    for (int k = 2; k <= SEG; k <<= 1) {
        for (int j = k >> 1; j > 0; j >>= 1) {
            for (int l = t; l < SEG; l += 512) {
                int ixj = l ^ j;
                if (ixj > l) {
                    unsigned long long a = s[l], b = s[ixj];
                    bool dirDesc = (((ihead + l) & k) == 0);
                    bool sw = dirDesc ? (a < b) : (a > b);
                    if (sw) { s[l] = b; s[ixj] = a; }
                }
            }
            __syncthreads();
        }
    }
    for (int l = t; l < SEG; l += 512) buf[base + l] = s[l];
}

// global compare-exchange step (cross-segment j)
__global__ void global_merge_kernel(unsigned long long* __restrict__ buf, int k, int j, int nH) {
    int gid = blockIdx.x * blockDim.x + threadIdx.x;
    if (gid >= nH * NN) return;
    int i = gid & (NN - 1);
    int ixj = i ^ j;
    if (ixj <= i) return;
    int hbase = gid & ~(NN - 1);
    unsigned long long a = buf[hbase + i], b = buf[hbase + ixj];
    bool dirDesc = ((i & k) == 0);
    bool sw = dirDesc ? (a < b) : (a > b);
    if (sw) { buf[hbase + i] = b; buf[hbase + ixj] = a; }
}

// remaining in-segment steps of stage k: j = jstart .. 1
__global__ __launch_bounds__(512) void local_merge_kernel(
    unsigned long long* __restrict__ buf, int k, int jstart)
{
    __shared__ unsigned long long s[SEG];
    int base = blockIdx.x * SEG;
    int ihead = base & (NN - 1);
    int t = threadIdx.x;
    for (int l = t; l < SEG; l += 512) s[l] = buf[base + l];
    __syncthreads();
    for (int j = jstart; j > 0; j >>= 1) {
        for (int l = t; l < SEG; l += 512) {
            int ixj = l ^ j;
            if (ixj > l) {
                unsigned long long a = s[l], b = s[ixj];
                bool dirDesc = (((ihead + l) & k) == 0);
                bool sw = dirDesc ? (a < b) : (a > b);
                if (sw) { s[l] = b; s[ixj] = a; }
            }
        }
        __syncthreads();
    }
    for (int l = t; l < SEG; l += 512) buf[base + l] = s[l];
}

// unpack: key (float, desc), perm, w = exp(key - keymax)
__global__ void sort_epilogue_kernel(
    const unsigned long long* __restrict__ buf,
    float* __restrict__ key, int* __restrict__ perm, float* __restrict__ w, int nH)
{
    int gid = blockIdx.x * blockDim.x + threadIdx.x;
    if (gid >= nH * NN) return;
    int h = gid >> 13;
    unsigned long long v = buf[gid];
    float kf = float_of_ord((unsigned int)(v >> 32));
    float kmax = float_of_ord((unsigned int)(buf[h * NN] >> 32));
    key[gid] = kf;
    perm[gid] = (int)(unsigned int)(v & 0xFFFFFFFFu);
    w[gid] = expf(kf - kmax);
}

__global__ void col_mean_kernel(const float* __restrict__ Wh, int ld, int F, float* __restrict__ mean) {
    int d = blockIdx.x, h = blockIdx.y;
    float s = 0.f;
    for (int i = threadIdx.x; i < NN; i += blockDim.x)
        s += Wh[(size_t)i * ld + h * F + d];
    __shared__ float red[256];
    red[threadIdx.x] = s;
    __syncthreads();
    for (int o = 128; o; o >>= 1) {
        if (threadIdx.x < o) red[threadIdx.x] += red[threadIdx.x + o];
        __syncthreads();
    }
    if (threadIdx.x == 0) mean[h * 64 + d] = red[0] / (float)NN;
}

__global__ void chunk_sums_kernel(
    const float* __restrict__ Wh, int ld, int F,
    const int* __restrict__ perm, const float* __restrict__ w,
    float* __restrict__ chunkP, float* __restrict__ chunkS)
{
    int c = blockIdx.x, h = blockIdx.y, d = threadIdx.x;
    const int* pm = perm + h * NN + c * CHUNK;
    const float* ww = w + h * NN + c * CHUNK;
    float acc = 0.f, accS = 0.f;
    for (int r = 0; r < CHUNK; r++) {
        float wr = ww[r];
        if (d < F) acc += wr * Wh[(size_t)pm[r] * ld + h * F + d];
        if (d == 0) accS += wr;
    }
    if (d < F) chunkP[(h * NCHUNKS + c) * 64 + d] = acc;
    if (d == 0) chunkS[h * NCHUNKS + c] = accS;
}

__global__ void scan_chunks_kernel(float* __restrict__ chunkP, float* __restrict__ chunkS, int F) {
    int h = blockIdx.x, d = threadIdx.x;
    if (d < F) {
        float acc = 0.f;
        for (int c = 0; c < NCHUNKS; c++) {
            int idx = (h * NCHUNKS + c) * 64 + d;
            float t = chunkP[idx]; chunkP[idx] = acc; acc += t;
        }
    }
    if (d == 0) {
        float acc = 0.f;
        for (int c = 0; c < NCHUNKS; c++) {
            int idx = h * NCHUNKS + c;
            float t = chunkS[idx]; chunkS[idx] = acc; acc += t;
        }
    }
}

__global__ void write_prefix_kernel(
    const float* __restrict__ Wh, int ld, int F,
    const int* __restrict__ perm, const float* __restrict__ w,
    const float* __restrict__ chunkP, const float* __restrict__ chunkS,
    float* __restrict__ P, float* __restrict__ S)
{
    int c = blockIdx.x, h = blockIdx.y, d = threadIdx.x;
    const int* pm = perm + h * NN + c * CHUNK;
    const float* ww = w + h * NN + c * CHUNK;
    float acc = (d < F) ? chunkP[(h * NCHUNKS + c) * 64 + d] : 0.f;
    float accS = chunkS[h * NCHUNKS + c];
    float* Ph = P + (size_t)h * (NN + 1) * F;
    float* Sh = S + (size_t)h * (NN + 1);
    for (int r = 0; r < CHUNK; r++) {
        float wr = ww[r];
        if (d < F) {
            acc += wr * Wh[(size_t)pm[r] * ld + h * F + d];
            Ph[(size_t)(c * CHUNK + r + 1) * F + d] = acc;
        }
        if (d == 0) { accS += wr; Sh[c * CHUNK + r + 1] = accS; }
    }
}

__global__ void apply_attn_kernel(
    const float* __restrict__ key, const float* __restrict__ f1,
    const float* __restrict__ P, const float* __restrict__ S,
    const float* __restrict__ mean, int F, int nHeads,
    float* __restrict__ out, int ldOut)
{
    int g = (blockIdx.x * blockDim.x + threadIdx.x) >> 6;
    int d = threadIdx.x & 63;
    int total = NN * nHeads;
    if (g >= total) return;
    int h = g % nHeads;
    int i = g / nHeads;
    const float* kh = key + h * NN;
    float t = f1[h * NN + i];
    int lo = 0, hi = NN;
    while (lo < hi) {
        int mid = (lo + hi) >> 1;
        if (t + kh[mid] > 0.f) lo = mid + 1; else hi = mid;
    }
    int c = lo;
    if (d < F) {
        float v;
        if (c > 0) {
            v = P[((size_t)h * (NN + 1) + c) * F + d] / S[(size_t)h * (NN + 1) + c];
        } else {
            v = mean[h * 64 + d];
        }
        v = (v > 0.f) ? v : (expf(v) - 1.f);
        out[(size_t)i * ldOut + h * F + d] = v;
    }
}

__global__ void log_softmax_kernel(const float* __restrict__ X, float* __restrict__ out) {
    int i = blockIdx.x * (blockDim.x >> 5) + (threadIdx.x >> 5);
    int lane = threadIdx.x & 31;
    if (i >= NN) return;
    const float* row = X + (size_t)i * NCLASS;
    float v0 = (lane < NCLASS) ? row[lane] : -INFINITY;
    float v1 = (lane + 32 < NCLASS) ? row[lane + 32] : -INFINITY;
    float mx = fmaxf(v0, v1);
#pragma unroll
    for (int o = 16; o; o >>= 1) mx = fmaxf(mx, __shfl_xor_sync(0xFFFFFFFFu, mx, o));
    float se = 0.f;
    if (lane < NCLASS) se += expf(v0 - mx);
    if (lane + 32 < NCLASS) se += expf(v1 - mx);
#pragma unroll
    for (int o = 16; o; o >>= 1) se += __shfl_xor_sync(0xFFFFFFFFu, se, o);
    float lse = mx + logf(se);
    if (lane < NCLASS) out[(size_t)i * NCLASS + lane] = v0 - lse;
    if (lane + 32 < NCLASS) out[(size_t)i * NCLASS + lane + 32] = v1 - lse;
}

// ----------------------------- host launcher --------------------------------
static void run_sort(unsigned long long* buf, float* key, int* perm, float* w, int nH) {
    int nSeg = nH * NN / SEG;
    int nThr = nH * NN;
    local_sort_kernel<<<nSeg, 512>>>(buf);
    global_merge_kernel<<<(nThr + 255) / 256, 256>>>(buf, 4096, 2048, nH);
    local_merge_kernel<<<nSeg, 512>>>(buf, 4096, 1024);
    global_merge_kernel<<<(nThr + 255) / 256, 256>>>(buf, 8192, 4096, nH);
    global_merge_kernel<<<(nThr + 255) / 256, 256>>>(buf, 8192, 2048, nH);
    local_merge_kernel<<<nSeg, 512>>>(buf, 8192, 1024);
    sort_epilogue_kernel<<<(nThr + 255) / 256, 256>>>(buf, key, perm, w, nH);
}

extern "C" void kernel_launch(void* const* d_in, const int* in_sizes, int n_in,
                              void* d_out, int out_size)
{
    const float* x       = (const float*)d_in[0];
    const float* W_heads = (const float*)d_in[2];
    const float* a_heads = (const float*)d_in[3];
    const float* W_out   = (const float*)d_in[4];
    const float* a_out   = (const float*)d_in[5];
    float* out = (float*)d_out;

    float *Bp, *Wh1, *H, *Wh2, *O2, *f1, *key, *w, *meanb, *P, *S, *P2, *S2, *chunkP, *chunkS;
    int* perm;
    unsigned long long* sbuf;
    cudaGetSymbolAddress((void**)&Bp,    g_Bpack);
    cudaGetSymbolAddress((void**)&Wh1,   g_Wh1);
    cudaGetSymbolAddress((void**)&H,     g_H);
    cudaGetSymbolAddress((void**)&Wh2,   g_Wh2);
    cudaGetSymbolAddress((void**)&O2,    g_O2);
    cudaGetSymbolAddress((void**)&f1,    g_f1);
    cudaGetSymbolAddress((void**)&key,   g_key);
    cudaGetSymbolAddress((void**)&perm,  g_perm);
    cudaGetSymbolAddress((void**)&w,     g_w);
    cudaGetSymbolAddress((void**)&meanb, g_mean);
    cudaGetSymbolAddress((void**)&P,     g_P);
    cudaGetSymbolAddress((void**)&S,     g_S);
    cudaGetSymbolAddress((void**)&P2,    g_P2);
    cudaGetSymbolAddress((void**)&S2,    g_S2);
    cudaGetSymbolAddress((void**)&chunkP, g_chunkP);
    cudaGetSymbolAddress((void**)&chunkS, g_chunkS);
    cudaGetSymbolAddress((void**)&sbuf,  g_sortbuf);

    // ---------------- layer 1 (8 heads fused) ----------------
    repack_W_kernel<<<(NFEAT * NHEADS * NHID + 255) / 256, 256>>>(W_heads, Bp);
    {
        dim3 grid((NHEADS * NHID + BN - 1) / BN, (NN + BM - 1) / BM);
        sgemm_kernel<<<grid, 256>>>(NN, NHEADS * NHID, NFEAT, x, Bp, Wh1);
    }
    compute_f_kernel<<<(NN * NHEADS * 32) / 128, 128>>>(Wh1, NHEADS * NHID, NHID,
                                                        a_heads, 2 * NHID, NHEADS, f1, sbuf);
    run_sort(sbuf, key, perm, w, NHEADS);
    col_mean_kernel<<<dim3(NHID, NHEADS), 256>>>(Wh1, NHEADS * NHID, NHID, meanb);
    chunk_sums_kernel<<<dim3(NCHUNKS, NHEADS), 64>>>(Wh1, NHEADS * NHID, NHID, perm, w, chunkP, chunkS);
    scan_chunks_kernel<<<NHEADS, 64>>>(chunkP, chunkS, NHID);
    write_prefix_kernel<<<dim3(NCHUNKS, NHEADS), 64>>>(Wh1, NHEADS * NHID, NHID, perm, w,
                                                       chunkP, chunkS, P, S);
    apply_attn_kernel<<<(NN * NHEADS * 64) / 256, 256>>>(key, f1, P, S, meanb, NHID, NHEADS,
                                                         H, NHEADS * NHID);

    // ---------------- layer 2 (output head, F = 40) ----------------
    {
        dim3 grid((NCLASS + BN - 1) / BN, (NN + BM - 1) / BM);
        sgemm_kernel<<<grid, 256>>>(NN, NCLASS, NHEADS * NHID, H, W_out, Wh2);
    }
    compute_f_kernel<<<(NN * 32 + 127) / 128, 128>>>(Wh2, NCLASS, NCLASS, a_out, 2 * NCLASS, 1, f1, sbuf);
    run_sort(sbuf, key, perm, w, 1);
    col_mean_kernel<<<dim3(NCLASS, 1), 256>>>(Wh2, NCLASS, NCLASS, meanb);
    chunk_sums_kernel<<<dim3(NCHUNKS, 1), 64>>>(Wh2, NCLASS, NCLASS, perm, w, chunkP, chunkS);
    scan_chunks_kernel<<<1, 64>>>(chunkP, chunkS, NCLASS);
    write_prefix_kernel<<<dim3(NCHUNKS, 1), 64>>>(Wh2, NCLASS, NCLASS, perm, w, chunkP, chunkS, P2, S2);
    apply_attn_kernel<<<(NN * 64) / 256, 256>>>(key, f1, P2, S2, meanb, NCLASS, 1, O2, NCLASS);

    log_softmax_kernel<<<(NN + 7) / 8, 256>>>(O2, out);
}